// round 7
// baseline (speedup 1.0000x reference)
#include <cuda_runtime.h>
#include <cstdint>

#define NN 50000
#define NE 800000
#define DD 256
#define SCAN_BLK 512
#define SCAN_NB  ((NN + SCAN_BLK - 1) / SCAN_BLK)   // 98
#define AST 140   // smem row stride (words): conflict-free mma fragment loads

// Static scratch (no allocations allowed): ~116 MB.
__device__ float g_x[NN * DD];      // current activations
__device__ float g_h[NN * DD];      // post-GEMM, pre-aggregation
__device__ float g_dinv[NN];
__device__ int   g_src[NE];
__device__ int   g_dst[NE];
__device__ int   g_esrc[NE];        // CSR: src ids grouped by dst
__device__ float g_enorm[NE];       // CSR: dinv[s]*dinv[d] per edge
__device__ int   g_cnt[NN];         // in-degree (edges only)
__device__ int   g_rowstart[NN + 1];
__device__ int   g_fill[NN];
__device__ int   g_bsum[SCAN_NB];
__device__ int   g_boff[SCAN_NB];
__device__ int   g_odd_nonzero;     // dtype sniffer flag

// ---------------------------------------------------------------------------
// Setup: dtype sniff, decode+histogram, 3-pass scan, CSR fill (+edge norm)
// ---------------------------------------------------------------------------
__global__ void init_kernel() {
    int i = blockIdx.x * blockDim.x + threadIdx.x;
    if (i < NN) g_cnt[i] = 0;
    if (i == 0) g_odd_nonzero = 0;
}

// Sample first 8192 int32 words; int64 data => all odd words are zero.
__global__ void detect_kernel(const int* __restrict__ ei32) {
    int i = blockIdx.x * blockDim.x + threadIdx.x;   // 0..8191
    if ((i & 1) && ei32[i] != 0) atomicOr(&g_odd_nonzero, 1);
}

__global__ void decode_hist_kernel(const int* __restrict__ ei32) {
    int e = blockIdx.x * blockDim.x + threadIdx.x;
    if (e >= NE) return;
    int s, d;
    if (g_odd_nonzero) {            // genuinely int32: [src[NE] | dst[NE]]
        s = ei32[e];
        d = ei32[NE + e];
    } else {                        // int64: low words at even offsets
        s = ei32[2 * e];
        d = ei32[2 * (NE + e)];
    }
    g_src[e] = s;
    g_dst[e] = d;
    atomicAdd(&g_cnt[d], 1);
}

// Pass 1: per-block sums of g_cnt
__global__ void __launch_bounds__(SCAN_BLK) partial_sum_kernel() {
    __shared__ int s[SCAN_BLK];
    int t = threadIdx.x;
    int i = blockIdx.x * SCAN_BLK + t;
    s[t] = (i < NN) ? g_cnt[i] : 0;
    __syncthreads();
    for (int off = SCAN_BLK / 2; off > 0; off >>= 1) {
        if (t < off) s[t] += s[t + off];
        __syncthreads();
    }
    if (t == 0) g_bsum[blockIdx.x] = s[0];
}

// Pass 2: exclusive scan of 98 block sums (1 small block)
__global__ void __launch_bounds__(128) scan_partials_kernel() {
    __shared__ int s[128];
    int t = threadIdx.x;
    int v = (t < SCAN_NB) ? g_bsum[t] : 0;
    s[t] = v;
    __syncthreads();
    for (int off = 1; off < 128; off <<= 1) {
        int x = s[t];
        int add = (t >= off) ? s[t - off] : 0;
        __syncthreads();
        s[t] = x + add;
        __syncthreads();
    }
    if (t < SCAN_NB) g_boff[t] = s[t] - v;   // exclusive
}

// Pass 3: per-block local scan + offset; writes rowstart, dinv, fill
__global__ void __launch_bounds__(SCAN_BLK) write_rows_kernel() {
    __shared__ int s[SCAN_BLK];
    int t = threadIdx.x;
    int i = blockIdx.x * SCAN_BLK + t;
    int v = (i < NN) ? g_cnt[i] : 0;
    s[t] = v;
    __syncthreads();
    for (int off = 1; off < SCAN_BLK; off <<= 1) {
        int x = s[t];
        int add = (t >= off) ? s[t - off] : 0;
        __syncthreads();
        s[t] = x + add;
        __syncthreads();
    }
    if (i < NN) {
        g_rowstart[i] = g_boff[blockIdx.x] + s[t] - v;
        g_fill[i] = 0;
        g_dinv[i] = rsqrtf((float)v + 1.0f);   // +1 self loop
    }
    if (i == 0) g_rowstart[NN] = NE;
}

// Fill CSR; also precompute per-edge norm (dinv ready after write_rows).
__global__ void fill_kernel() {
    int e = blockIdx.x * blockDim.x + threadIdx.x;
    if (e >= NE) return;
    int s = g_src[e];
    int d = g_dst[e];
    int pos = g_rowstart[d] + atomicAdd(&g_fill[d], 1);
    g_esrc[pos]  = s;
    g_enorm[pos] = g_dinv[s] * g_dinv[d];
}

// ---------------------------------------------------------------------------
// TF32 tensor-core GEMM: C[M,256] = A[M,256] @ B[256,256] (+bias, +relu)
// 128x128 tile, 256 threads (8 warps, 2M x 4N), warp tile 64x32,
// mma.sync.m16n8k8.tf32, BK=16, double-buffered smem (1 sync/chunk).
// a_sel: 0 -> A = Ain (external), 1 -> A = g_x ; C = g_x (c_sel=0) / g_h (1)
// ---------------------------------------------------------------------------
__device__ __forceinline__ uint32_t f2tf32(float f) {
    uint32_t u;
    asm("cvt.rna.tf32.f32 %0, %1;" : "=r"(u) : "f"(f));
    return u;
}

__global__ void __launch_bounds__(256)
gemm_kernel(const float* __restrict__ Ain, const float* __restrict__ B,
            const float* __restrict__ bias, int a_sel, int c_sel, int relu)
{
    const float* A = (a_sel == 0) ? Ain : g_x;
    float*       C = (c_sel == 0) ? g_x : g_h;

    __shared__ uint32_t As[2][16 * AST];   // [buf][k][m], tf32 bits
    __shared__ uint32_t Bs[2][16 * AST];   // [buf][k][n], tf32 bits

    const int tid  = threadIdx.x;
    const int lane = tid & 31;
    const int w    = tid >> 5;
    const int mw   = (w & 1) << 6;      // warp M offset: 0 / 64
    const int nw   = (w >> 1) << 5;     // warp N offset: 0/32/64/96
    const int gid  = lane >> 2;         // 0..7
    const int tg   = lane & 3;          // 0..3
    const int row0 = blockIdx.x * 128;
    const int col0 = blockIdx.y * 128;

    // per-thread staging indices
    const int idx0 = tid,        idx1 = tid + 256;
    const int ar0 = idx0 >> 2,   ak0 = (idx0 & 3) * 4;
    const int ar1 = idx1 >> 2,   ak1 = (idx1 & 3) * 4;
    const int bk0 = idx0 >> 5,   bn0 = (idx0 & 31) * 4;
    const int bk1 = idx1 >> 5,   bn1 = (idx1 & 31) * 4;

    float acc[4][4][4];
#pragma unroll
    for (int mt = 0; mt < 4; mt++)
#pragma unroll
        for (int nt = 0; nt < 4; nt++)
#pragma unroll
            for (int q = 0; q < 4; q++) acc[mt][nt][q] = 0.0f;

    float4 av0, av1, bv0, bv1;

    // prefetch + store chunk 0
    {
        int r0 = row0 + ar0, r1 = row0 + ar1;
        av0 = (r0 < NN) ? *(const float4*)&A[(size_t)r0 * DD + ak0] : make_float4(0,0,0,0);
        av1 = (r1 < NN) ? *(const float4*)&A[(size_t)r1 * DD + ak1] : make_float4(0,0,0,0);
        bv0 = *(const float4*)&B[(size_t)bk0 * DD + col0 + bn0];
        bv1 = *(const float4*)&B[(size_t)bk1 * DD + col0 + bn1];
        As[0][(ak0 + 0) * AST + ar0] = f2tf32(av0.x);
        As[0][(ak0 + 1) * AST + ar0] = f2tf32(av0.y);
        As[0][(ak0 + 2) * AST + ar0] = f2tf32(av0.z);
        As[0][(ak0 + 3) * AST + ar0] = f2tf32(av0.w);
        As[0][(ak1 + 0) * AST + ar1] = f2tf32(av1.x);
        As[0][(ak1 + 1) * AST + ar1] = f2tf32(av1.y);
        As[0][(ak1 + 2) * AST + ar1] = f2tf32(av1.z);
        As[0][(ak1 + 3) * AST + ar1] = f2tf32(av1.w);
        uint4 bu;
        bu.x = f2tf32(bv0.x); bu.y = f2tf32(bv0.y); bu.z = f2tf32(bv0.z); bu.w = f2tf32(bv0.w);
        *(uint4*)&Bs[0][bk0 * AST + bn0] = bu;
        bu.x = f2tf32(bv1.x); bu.y = f2tf32(bv1.y); bu.z = f2tf32(bv1.z); bu.w = f2tf32(bv1.w);
        *(uint4*)&Bs[0][bk1 * AST + bn1] = bu;
    }
    __syncthreads();

    for (int c = 0; c < 16; c++) {
        const int cur = c & 1;
        // prefetch chunk c+1 (latency hidden by the MMAs below)
        if (c < 15) {
            int k0 = (c + 1) * 16;
            int r0 = row0 + ar0, r1 = row0 + ar1;
            av0 = (r0 < NN) ? *(const float4*)&A[(size_t)r0 * DD + k0 + ak0] : make_float4(0,0,0,0);
            av1 = (r1 < NN) ? *(const float4*)&A[(size_t)r1 * DD + k0 + ak1] : make_float4(0,0,0,0);
            bv0 = *(const float4*)&B[(size_t)(k0 + bk0) * DD + col0 + bn0];
            bv1 = *(const float4*)&B[(size_t)(k0 + bk1) * DD + col0 + bn1];
        }
        // compute chunk c: 2 k8-substeps, 4x4 mma each
#pragma unroll
        for (int sub = 0; sub < 16; sub += 8) {
            uint32_t bf[4][2];
#pragma unroll
            for (int nt = 0; nt < 4; nt++) {
                bf[nt][0] = Bs[cur][(sub + tg) * AST + nw + nt * 8 + gid];
                bf[nt][1] = Bs[cur][(sub + tg + 4) * AST + nw + nt * 8 + gid];
            }
#pragma unroll
            for (int mt = 0; mt < 4; mt++) {
                uint32_t a0 = As[cur][(sub + tg) * AST + mw + mt * 16 + gid];
                uint32_t a1 = As[cur][(sub + tg) * AST + mw + mt * 16 + gid + 8];
                uint32_t a2 = As[cur][(sub + tg + 4) * AST + mw + mt * 16 + gid];
                uint32_t a3 = As[cur][(sub + tg + 4) * AST + mw + mt * 16 + gid + 8];
#pragma unroll
                for (int nt = 0; nt < 4; nt++) {
                    asm("mma.sync.aligned.m16n8k8.row.col.f32.tf32.tf32.f32 "
                        "{%0,%1,%2,%3}, {%4,%5,%6,%7}, {%8,%9}, {%0,%1,%2,%3};"
                        : "+f"(acc[mt][nt][0]), "+f"(acc[mt][nt][1]),
                          "+f"(acc[mt][nt][2]), "+f"(acc[mt][nt][3])
                        : "r"(a0), "r"(a1), "r"(a2), "r"(a3),
                          "r"(bf[nt][0]), "r"(bf[nt][1]));
                }
            }
        }
        // store chunk c+1 to the other buffer, then one sync
        if (c < 15) {
            const int nxt = cur ^ 1;
            As[nxt][(ak0 + 0) * AST + ar0] = f2tf32(av0.x);
            As[nxt][(ak0 + 1) * AST + ar0] = f2tf32(av0.y);
            As[nxt][(ak0 + 2) * AST + ar0] = f2tf32(av0.z);
            As[nxt][(ak0 + 3) * AST + ar0] = f2tf32(av0.w);
            As[nxt][(ak1 + 0) * AST + ar1] = f2tf32(av1.x);
            As[nxt][(ak1 + 1) * AST + ar1] = f2tf32(av1.y);
            As[nxt][(ak1 + 2) * AST + ar1] = f2tf32(av1.z);
            As[nxt][(ak1 + 3) * AST + ar1] = f2tf32(av1.w);
            uint4 bu;
            bu.x = f2tf32(bv0.x); bu.y = f2tf32(bv0.y); bu.z = f2tf32(bv0.z); bu.w = f2tf32(bv0.w);
            *(uint4*)&Bs[nxt][bk0 * AST + bn0] = bu;
            bu.x = f2tf32(bv1.x); bu.y = f2tf32(bv1.y); bu.z = f2tf32(bv1.z); bu.w = f2tf32(bv1.w);
            *(uint4*)&Bs[nxt][bk1 * AST + bn1] = bu;
            __syncthreads();
        }
    }

    // epilogue: c0,c1 -> (row gid, cols 2tg,2tg+1); c2,c3 -> row gid+8
    float2 bb[4];
    if (bias) {
#pragma unroll
        for (int nt = 0; nt < 4; nt++) {
            int cc = col0 + nw + nt * 8 + 2 * tg;
            bb[nt].x = bias[cc];
            bb[nt].y = bias[cc + 1];
        }
    }
#pragma unroll
    for (int mt = 0; mt < 4; mt++) {
        int r = row0 + mw + mt * 16 + gid;
#pragma unroll
        for (int nt = 0; nt < 4; nt++) {
            int cc = col0 + nw + nt * 8 + 2 * tg;
            float2 v0 = make_float2(acc[mt][nt][0], acc[mt][nt][1]);
            float2 v1 = make_float2(acc[mt][nt][2], acc[mt][nt][3]);
            if (bias) {
                v0.x += bb[nt].x; v0.y += bb[nt].y;
                v1.x += bb[nt].x; v1.y += bb[nt].y;
            }
            if (relu) {
                v0.x = fmaxf(v0.x, 0.f); v0.y = fmaxf(v0.y, 0.f);
                v1.x = fmaxf(v1.x, 0.f); v1.y = fmaxf(v1.y, 0.f);
            }
            if (r < NN)     *(float2*)&C[(size_t)r * DD + cc]       = v0;
            if (r + 8 < NN) *(float2*)&C[(size_t)(r + 8) * DD + cc] = v1;
        }
    }
}

// ---------------------------------------------------------------------------
// Fused CSR aggregation: one warp per dst node, 4-edge unroll, precomputed norms.
//   o[d] = relu( bias + dinv[d]^2 * h[d] + sum_{e in CSR(d)} enorm[e] * h[esrc[e]] )
// ---------------------------------------------------------------------------
__global__ void __launch_bounds__(256)
aggregate_kernel(const float* __restrict__ bias, float* __restrict__ Oin, int o_sel)
{
    float* o = (o_sel == 0) ? g_x : Oin;
    int warp = (blockIdx.x * blockDim.x + threadIdx.x) >> 5;
    int lane = threadIdx.x & 31;
    if (warp >= NN) return;
    const int d = warp;
    const float dv = g_dinv[d];

    // self-loop init
    const float4* hd = (const float4*)(g_h + (size_t)d * DD);
    float4 a0 = hd[lane];
    float4 a1 = hd[lane + 32];
    const float s2 = dv * dv;
    a0.x *= s2; a0.y *= s2; a0.z *= s2; a0.w *= s2;
    a1.x *= s2; a1.y *= s2; a1.z *= s2; a1.w *= s2;

    const int start = g_rowstart[d];
    const int end   = g_rowstart[d + 1];
    int i = start;
    for (; i + 4 <= end; i += 4) {
        int   s0 = g_esrc[i],      s1 = g_esrc[i + 1];
        int   s2i = g_esrc[i + 2], s3 = g_esrc[i + 3];
        float n0 = g_enorm[i],     n1 = g_enorm[i + 1];
        float n2 = g_enorm[i + 2], n3 = g_enorm[i + 3];
        const float4* h0 = (const float4*)(g_h + (size_t)s0 * DD);
        const float4* h1 = (const float4*)(g_h + (size_t)s1 * DD);
        const float4* h2 = (const float4*)(g_h + (size_t)s2i * DD);
        const float4* h3 = (const float4*)(g_h + (size_t)s3 * DD);
        float4 v00 = h0[lane], v01 = h0[lane + 32];
        float4 v10 = h1[lane], v11 = h1[lane + 32];
        float4 v20 = h2[lane], v21 = h2[lane + 32];
        float4 v30 = h3[lane], v31 = h3[lane + 32];
        a0.x += n0 * v00.x; a0.y += n0 * v00.y; a0.z += n0 * v00.z; a0.w += n0 * v00.w;
        a1.x += n0 * v01.x; a1.y += n0 * v01.y; a1.z += n0 * v01.z; a1.w += n0 * v01.w;
        a0.x += n1 * v10.x; a0.y += n1 * v10.y; a0.z += n1 * v10.z; a0.w += n1 * v10.w;
        a1.x += n1 * v11.x; a1.y += n1 * v11.y; a1.z += n1 * v11.z; a1.w += n1 * v11.w;
        a0.x += n2 * v20.x; a0.y += n2 * v20.y; a0.z += n2 * v20.z; a0.w += n2 * v20.w;
        a1.x += n2 * v21.x; a1.y += n2 * v21.y; a1.z += n2 * v21.z; a1.w += n2 * v21.w;
        a0.x += n3 * v30.x; a0.y += n3 * v30.y; a0.z += n3 * v30.z; a0.w += n3 * v30.w;
        a1.x += n3 * v31.x; a1.y += n3 * v31.y; a1.z += n3 * v31.z; a1.w += n3 * v31.w;
    }
    for (; i < end; i++) {
        int s0 = g_esrc[i];
        float n0 = g_enorm[i];
        const float4* h0 = (const float4*)(g_h + (size_t)s0 * DD);
        float4 v00 = h0[lane], v01 = h0[lane + 32];
        a0.x += n0 * v00.x; a0.y += n0 * v00.y; a0.z += n0 * v00.z; a0.w += n0 * v00.w;
        a1.x += n0 * v01.x; a1.y += n0 * v01.y; a1.z += n0 * v01.z; a1.w += n0 * v01.w;
    }

    // bias + relu + store
    float4 b0 = ((const float4*)bias)[lane];
    float4 b1 = ((const float4*)bias)[lane + 32];
    a0.x = fmaxf(a0.x + b0.x, 0.f); a0.y = fmaxf(a0.y + b0.y, 0.f);
    a0.z = fmaxf(a0.z + b0.z, 0.f); a0.w = fmaxf(a0.w + b0.w, 0.f);
    a1.x = fmaxf(a1.x + b1.x, 0.f); a1.y = fmaxf(a1.y + b1.y, 0.f);
    a1.z = fmaxf(a1.z + b1.z, 0.f); a1.w = fmaxf(a1.w + b1.w, 0.f);
    float4* orow = (float4*)(o + (size_t)d * DD);
    orow[lane] = a0;
    orow[lane + 32] = a1;
}

// ---------------------------------------------------------------------------
// Launch — kernels only; no runtime API calls (graph-capture safe).
// ---------------------------------------------------------------------------
extern "C" void kernel_launch(void* const* d_in, const int* in_sizes, int n_in,
                              void* d_out, int out_size)
{
    const float* input  = (const float*)d_in[0];
    const int*   ei32   = (const int*)d_in[1];     // int32 view; dtype sniffed on device
    const float* weight = (const float*)d_in[2];
    const float* bias   = (const float*)d_in[3];
    const float* conv_w = (const float*)d_in[4];
    const float* conv_b = (const float*)d_in[5];
    float*       out    = (float*)d_out;

    // CSR build
    init_kernel<<<(NN + 255) / 256, 256>>>();
    detect_kernel<<<8192 / 256, 256>>>(ei32);
    decode_hist_kernel<<<(NE + 255) / 256, 256>>>(ei32);
    partial_sum_kernel<<<SCAN_NB, SCAN_BLK>>>();
    scan_partials_kernel<<<1, 128>>>();
    write_rows_kernel<<<SCAN_NB, SCAN_BLK>>>();
    fill_kernel<<<(NE + 255) / 256, 256>>>();

    dim3 ggrid((NN + 127) / 128, DD / 128);

    // x = relu(input @ W + b)   (A = input, C = g_x)
    gemm_kernel<<<ggrid, 256>>>(input, weight, bias, /*a_sel=*/0, /*c_sel=*/0, /*relu=*/1);

    const int agg_blocks = (NN * 32 + 255) / 256;   // warp per node
    for (int l = 0; l < 2; l++) {
        // h = x @ conv_w[l]   (A = g_x, C = g_h)
        gemm_kernel<<<ggrid, 256>>>(nullptr, conv_w + (size_t)l * DD * DD,
                                    nullptr, /*a_sel=*/1, /*c_sel=*/1, /*relu=*/0);
        // fused: self-loop + neighbor gather + bias + relu
        aggregate_kernel<<<agg_blocks, 256>>>(conv_b + l * DD,
                                              out, /*o_sel=*/(l == 0) ? 0 : 1);
    }
}

// round 8
// speedup vs baseline: 1.0551x; 1.0551x over previous
#include <cuda_runtime.h>
#include <cstdint>

#define NN 50000
#define NE 800000
#define DD 256
#define SCAN_BLK 512
#define SCAN_NB  ((NN + SCAN_BLK - 1) / SCAN_BLK)   // 98
#define AST 140   // smem row stride (words): conflict-free mma fragment loads

// Static scratch (no allocations allowed): ~116 MB.
__device__ float g_x[NN * DD];      // current activations
__device__ float g_h[NN * DD];      // post-GEMM, pre-aggregation
__device__ float g_dinv[NN];
__device__ int   g_src[NE];
__device__ int   g_dst[NE];
__device__ int   g_esrc[NE];        // CSR: src ids grouped by dst
__device__ float g_enorm[NE];       // CSR: dinv[s]*dinv[d] per edge
__device__ int   g_cnt[NN];         // in-degree (edges only)
__device__ int   g_rowstart[NN + 1];
__device__ int   g_fill[NN];
__device__ int   g_bsum[SCAN_NB];
__device__ int   g_boff[SCAN_NB];
__device__ int   g_odd_nonzero;     // dtype sniffer flag

// ---------------------------------------------------------------------------
// Setup: dtype sniff, decode+histogram, 3-pass scan, CSR fill (+edge norm)
// ---------------------------------------------------------------------------
__global__ void init_kernel() {
    int i = blockIdx.x * blockDim.x + threadIdx.x;
    if (i < NN) g_cnt[i] = 0;
    if (i == 0) g_odd_nonzero = 0;
}

// Sample first 8192 int32 words; int64 data => all odd words are zero.
__global__ void detect_kernel(const int* __restrict__ ei32) {
    int i = blockIdx.x * blockDim.x + threadIdx.x;   // 0..8191
    if ((i & 1) && ei32[i] != 0) atomicOr(&g_odd_nonzero, 1);
}

__global__ void decode_hist_kernel(const int* __restrict__ ei32) {
    int e = blockIdx.x * blockDim.x + threadIdx.x;
    if (e >= NE) return;
    int s, d;
    if (g_odd_nonzero) {            // genuinely int32: [src[NE] | dst[NE]]
        s = ei32[e];
        d = ei32[NE + e];
    } else {                        // int64: low words at even offsets
        s = ei32[2 * e];
        d = ei32[2 * (NE + e)];
    }
    g_src[e] = s;
    g_dst[e] = d;
    atomicAdd(&g_cnt[d], 1);
}

// Pass 1: per-block sums of g_cnt
__global__ void __launch_bounds__(SCAN_BLK) partial_sum_kernel() {
    __shared__ int s[SCAN_BLK];
    int t = threadIdx.x;
    int i = blockIdx.x * SCAN_BLK + t;
    s[t] = (i < NN) ? g_cnt[i] : 0;
    __syncthreads();
    for (int off = SCAN_BLK / 2; off > 0; off >>= 1) {
        if (t < off) s[t] += s[t + off];
        __syncthreads();
    }
    if (t == 0) g_bsum[blockIdx.x] = s[0];
}

// Pass 2: exclusive scan of 98 block sums (1 small block)
__global__ void __launch_bounds__(128) scan_partials_kernel() {
    __shared__ int s[128];
    int t = threadIdx.x;
    int v = (t < SCAN_NB) ? g_bsum[t] : 0;
    s[t] = v;
    __syncthreads();
    for (int off = 1; off < 128; off <<= 1) {
        int x = s[t];
        int add = (t >= off) ? s[t - off] : 0;
        __syncthreads();
        s[t] = x + add;
        __syncthreads();
    }
    if (t < SCAN_NB) g_boff[t] = s[t] - v;   // exclusive
}

// Pass 3: per-block local scan + offset; writes rowstart, dinv, fill
__global__ void __launch_bounds__(SCAN_BLK) write_rows_kernel() {
    __shared__ int s[SCAN_BLK];
    int t = threadIdx.x;
    int i = blockIdx.x * SCAN_BLK + t;
    int v = (i < NN) ? g_cnt[i] : 0;
    s[t] = v;
    __syncthreads();
    for (int off = 1; off < SCAN_BLK; off <<= 1) {
        int x = s[t];
        int add = (t >= off) ? s[t - off] : 0;
        __syncthreads();
        s[t] = x + add;
        __syncthreads();
    }
    if (i < NN) {
        g_rowstart[i] = g_boff[blockIdx.x] + s[t] - v;
        g_fill[i] = 0;
        g_dinv[i] = rsqrtf((float)v + 1.0f);   // +1 self loop
    }
    if (i == 0) g_rowstart[NN] = NE;
}

// Fill CSR; also precompute per-edge norm (dinv ready after write_rows).
__global__ void fill_kernel() {
    int e = blockIdx.x * blockDim.x + threadIdx.x;
    if (e >= NE) return;
    int s = g_src[e];
    int d = g_dst[e];
    int pos = g_rowstart[d] + atomicAdd(&g_fill[d], 1);
    g_esrc[pos]  = s;
    g_enorm[pos] = g_dinv[s] * g_dinv[d];
}

// ---------------------------------------------------------------------------
// TF32 tensor-core GEMM: C[M,256] = A[M,256] @ B[256,256] (+bias, +relu)
// 128x128 tile, 256 threads (8 warps, 2M x 4N), warp tile 64x32,
// mma.sync.m16n8k8.tf32, BK=16, register-prefetch pipeline (single smem buf).
// a_sel: 0 -> A = Ain (external), 1 -> A = g_x ; C = g_x (c_sel=0) / g_h (1)
// ---------------------------------------------------------------------------
__device__ __forceinline__ uint32_t f2tf32(float f) {
    uint32_t u;
    asm("cvt.rna.tf32.f32 %0, %1;" : "=r"(u) : "f"(f));
    return u;
}

__global__ void __launch_bounds__(256)
gemm_kernel(const float* __restrict__ Ain, const float* __restrict__ B,
            const float* __restrict__ bias, int a_sel, int c_sel, int relu)
{
    const float* A = (a_sel == 0) ? Ain : g_x;
    float*       C = (c_sel == 0) ? g_x : g_h;

    __shared__ uint32_t As[16 * AST];   // [k][m], tf32 bits
    __shared__ uint32_t Bs[16 * AST];   // [k][n], tf32 bits

    const int tid  = threadIdx.x;
    const int lane = tid & 31;
    const int w    = tid >> 5;
    const int mw   = (w & 1) << 6;      // warp M offset: 0 / 64
    const int nw   = (w >> 1) << 5;     // warp N offset: 0/32/64/96
    const int gid  = lane >> 2;         // 0..7
    const int tg   = lane & 3;          // 0..3
    const int row0 = blockIdx.x * 128;
    const int col0 = blockIdx.y * 128;

    float acc[4][4][4];
#pragma unroll
    for (int mt = 0; mt < 4; mt++)
#pragma unroll
        for (int nt = 0; nt < 4; nt++)
#pragma unroll
            for (int q = 0; q < 4; q++) acc[mt][nt][q] = 0.0f;

    float4 av[2], bv[2];

    // prefetch chunk 0
#pragma unroll
    for (int i = 0; i < 2; i++) {
        int idx = tid + i * 256;
        int r = row0 + (idx >> 2);
        int kq = idx & 3;
        av[i] = (r < NN) ? *(const float4*)&A[(size_t)r * DD + kq * 4]
                         : make_float4(0.f, 0.f, 0.f, 0.f);
        int kr = idx >> 5, nq = idx & 31;
        bv[i] = *(const float4*)&B[(size_t)kr * DD + col0 + nq * 4];
    }

    for (int c = 0; c < 16; c++) {
        __syncthreads();
        // store prefetched chunk to smem (cvt to tf32)
#pragma unroll
        for (int i = 0; i < 2; i++) {
            int idx = tid + i * 256;
            int r = idx >> 2, kq = idx & 3;
            As[(kq * 4 + 0) * AST + r] = f2tf32(av[i].x);
            As[(kq * 4 + 1) * AST + r] = f2tf32(av[i].y);
            As[(kq * 4 + 2) * AST + r] = f2tf32(av[i].z);
            As[(kq * 4 + 3) * AST + r] = f2tf32(av[i].w);
            int kr = idx >> 5, nq = idx & 31;
            uint4 bu;
            bu.x = f2tf32(bv[i].x); bu.y = f2tf32(bv[i].y);
            bu.z = f2tf32(bv[i].z); bu.w = f2tf32(bv[i].w);
            *(uint4*)&Bs[kr * AST + nq * 4] = bu;
        }
        __syncthreads();
        // prefetch next chunk (latency hidden behind MMAs below)
        if (c < 15) {
            int k0 = (c + 1) * 16;
#pragma unroll
            for (int i = 0; i < 2; i++) {
                int idx = tid + i * 256;
                int r = row0 + (idx >> 2);
                int kq = idx & 3;
                av[i] = (r < NN) ? *(const float4*)&A[(size_t)r * DD + k0 + kq * 4]
                                 : make_float4(0.f, 0.f, 0.f, 0.f);
                int kr = idx >> 5, nq = idx & 31;
                bv[i] = *(const float4*)&B[(size_t)(k0 + kr) * DD + col0 + nq * 4];
            }
        }
        // compute: 2 k8-substeps, 4x4 mma each
#pragma unroll
        for (int sub = 0; sub < 16; sub += 8) {
            uint32_t bf[4][2];
#pragma unroll
            for (int nt = 0; nt < 4; nt++) {
                bf[nt][0] = Bs[(sub + tg) * AST + nw + nt * 8 + gid];
                bf[nt][1] = Bs[(sub + tg + 4) * AST + nw + nt * 8 + gid];
            }
#pragma unroll
            for (int mt = 0; mt < 4; mt++) {
                uint32_t a0 = As[(sub + tg) * AST + mw + mt * 16 + gid];
                uint32_t a1 = As[(sub + tg) * AST + mw + mt * 16 + gid + 8];
                uint32_t a2 = As[(sub + tg + 4) * AST + mw + mt * 16 + gid];
                uint32_t a3 = As[(sub + tg + 4) * AST + mw + mt * 16 + gid + 8];
#pragma unroll
                for (int nt = 0; nt < 4; nt++) {
                    asm("mma.sync.aligned.m16n8k8.row.col.f32.tf32.tf32.f32 "
                        "{%0,%1,%2,%3}, {%4,%5,%6,%7}, {%8,%9}, {%0,%1,%2,%3};"
                        : "+f"(acc[mt][nt][0]), "+f"(acc[mt][nt][1]),
                          "+f"(acc[mt][nt][2]), "+f"(acc[mt][nt][3])
                        : "r"(a0), "r"(a1), "r"(a2), "r"(a3),
                          "r"(bf[nt][0]), "r"(bf[nt][1]));
                }
            }
        }
    }

    // epilogue: c0,c1 -> (row gid, cols 2tg,2tg+1); c2,c3 -> row gid+8
    float2 bb[4];
    if (bias) {
#pragma unroll
        for (int nt = 0; nt < 4; nt++) {
            int cc = col0 + nw + nt * 8 + 2 * tg;
            bb[nt].x = bias[cc];
            bb[nt].y = bias[cc + 1];
        }
    }
#pragma unroll
    for (int mt = 0; mt < 4; mt++) {
        int r = row0 + mw + mt * 16 + gid;
#pragma unroll
        for (int nt = 0; nt < 4; nt++) {
            int cc = col0 + nw + nt * 8 + 2 * tg;
            float2 v0 = make_float2(acc[mt][nt][0], acc[mt][nt][1]);
            float2 v1 = make_float2(acc[mt][nt][2], acc[mt][nt][3]);
            if (bias) {
                v0.x += bb[nt].x; v0.y += bb[nt].y;
                v1.x += bb[nt].x; v1.y += bb[nt].y;
            }
            if (relu) {
                v0.x = fmaxf(v0.x, 0.f); v0.y = fmaxf(v0.y, 0.f);
                v1.x = fmaxf(v1.x, 0.f); v1.y = fmaxf(v1.y, 0.f);
            }
            if (r < NN)     *(float2*)&C[(size_t)r * DD + cc]       = v0;
            if (r + 8 < NN) *(float2*)&C[(size_t)(r + 8) * DD + cc] = v1;
        }
    }
}

// ---------------------------------------------------------------------------
// Fused CSR aggregation: one warp per dst node, 4-edge unroll, precomputed norms.
//   o[d] = relu( bias + dinv[d]^2 * h[d] + sum_{e in CSR(d)} enorm[e] * h[esrc[e]] )
// ---------------------------------------------------------------------------
__global__ void __launch_bounds__(256)
aggregate_kernel(const float* __restrict__ bias, float* __restrict__ Oin, int o_sel)
{
    float* o = (o_sel == 0) ? g_x : Oin;
    int warp = (blockIdx.x * blockDim.x + threadIdx.x) >> 5;
    int lane = threadIdx.x & 31;
    if (warp >= NN) return;
    const int d = warp;
    const float dv = g_dinv[d];

    // self-loop init
    const float4* hd = (const float4*)(g_h + (size_t)d * DD);
    float4 a0 = hd[lane];
    float4 a1 = hd[lane + 32];
    const float s2 = dv * dv;
    a0.x *= s2; a0.y *= s2; a0.z *= s2; a0.w *= s2;
    a1.x *= s2; a1.y *= s2; a1.z *= s2; a1.w *= s2;

    const int start = g_rowstart[d];
    const int end   = g_rowstart[d + 1];
    int i = start;
    for (; i + 4 <= end; i += 4) {
        int   s0 = g_esrc[i],      s1 = g_esrc[i + 1];
        int   s2i = g_esrc[i + 2], s3 = g_esrc[i + 3];
        float n0 = g_enorm[i],     n1 = g_enorm[i + 1];
        float n2 = g_enorm[i + 2], n3 = g_enorm[i + 3];
        const float4* h0 = (const float4*)(g_h + (size_t)s0 * DD);
        const float4* h1 = (const float4*)(g_h + (size_t)s1 * DD);
        const float4* h2 = (const float4*)(g_h + (size_t)s2i * DD);
        const float4* h3 = (const float4*)(g_h + (size_t)s3 * DD);
        float4 v00 = h0[lane], v01 = h0[lane + 32];
        float4 v10 = h1[lane], v11 = h1[lane + 32];
        float4 v20 = h2[lane], v21 = h2[lane + 32];
        float4 v30 = h3[lane], v31 = h3[lane + 32];
        a0.x += n0 * v00.x; a0.y += n0 * v00.y; a0.z += n0 * v00.z; a0.w += n0 * v00.w;
        a1.x += n0 * v01.x; a1.y += n0 * v01.y; a1.z += n0 * v01.z; a1.w += n0 * v01.w;
        a0.x += n1 * v10.x; a0.y += n1 * v10.y; a0.z += n1 * v10.z; a0.w += n1 * v10.w;
        a1.x += n1 * v11.x; a1.y += n1 * v11.y; a1.z += n1 * v11.z; a1.w += n1 * v11.w;
        a0.x += n2 * v20.x; a0.y += n2 * v20.y; a0.z += n2 * v20.z; a0.w += n2 * v20.w;
        a1.x += n2 * v21.x; a1.y += n2 * v21.y; a1.z += n2 * v21.z; a1.w += n2 * v21.w;
        a0.x += n3 * v30.x; a0.y += n3 * v30.y; a0.z += n3 * v30.z; a0.w += n3 * v30.w;
        a1.x += n3 * v31.x; a1.y += n3 * v31.y; a1.z += n3 * v31.z; a1.w += n3 * v31.w;
    }
    for (; i < end; i++) {
        int s0 = g_esrc[i];
        float n0 = g_enorm[i];
        const float4* h0 = (const float4*)(g_h + (size_t)s0 * DD);
        float4 v00 = h0[lane], v01 = h0[lane + 32];
        a0.x += n0 * v00.x; a0.y += n0 * v00.y; a0.z += n0 * v00.z; a0.w += n0 * v00.w;
        a1.x += n0 * v01.x; a1.y += n0 * v01.y; a1.z += n0 * v01.z; a1.w += n0 * v01.w;
    }

    // bias + relu + store
    float4 b0 = ((const float4*)bias)[lane];
    float4 b1 = ((const float4*)bias)[lane + 32];
    a0.x = fmaxf(a0.x + b0.x, 0.f); a0.y = fmaxf(a0.y + b0.y, 0.f);
    a0.z = fmaxf(a0.z + b0.z, 0.f); a0.w = fmaxf(a0.w + b0.w, 0.f);
    a1.x = fmaxf(a1.x + b1.x, 0.f); a1.y = fmaxf(a1.y + b1.y, 0.f);
    a1.z = fmaxf(a1.z + b1.z, 0.f); a1.w = fmaxf(a1.w + b1.w, 0.f);
    float4* orow = (float4*)(o + (size_t)d * DD);
    orow[lane] = a0;
    orow[lane + 32] = a1;
}

// ---------------------------------------------------------------------------
// Launch — kernels only; no runtime API calls (graph-capture safe).
// ---------------------------------------------------------------------------
extern "C" void kernel_launch(void* const* d_in, const int* in_sizes, int n_in,
                              void* d_out, int out_size)
{
    const float* input  = (const float*)d_in[0];
    const int*   ei32   = (const int*)d_in[1];     // int32 view; dtype sniffed on device
    const float* weight = (const float*)d_in[2];
    const float* bias   = (const float*)d_in[3];
    const float* conv_w = (const float*)d_in[4];
    const float* conv_b = (const float*)d_in[5];
    float*       out    = (float*)d_out;

    // CSR build
    init_kernel<<<(NN + 255) / 256, 256>>>();
    detect_kernel<<<8192 / 256, 256>>>(ei32);
    decode_hist_kernel<<<(NE + 255) / 256, 256>>>(ei32);
    partial_sum_kernel<<<SCAN_NB, SCAN_BLK>>>();
    scan_partials_kernel<<<1, 128>>>();
    write_rows_kernel<<<SCAN_NB, SCAN_BLK>>>();
    fill_kernel<<<(NE + 255) / 256, 256>>>();

    dim3 ggrid((NN + 127) / 128, DD / 128);

    // x = relu(input @ W + b)   (A = input, C = g_x)
    gemm_kernel<<<ggrid, 256>>>(input, weight, bias, /*a_sel=*/0, /*c_sel=*/0, /*relu=*/1);

    const int agg_blocks = (NN * 32 + 255) / 256;   // warp per node
    for (int l = 0; l < 2; l++) {
        // h = x @ conv_w[l]   (A = g_x, C = g_h)
        gemm_kernel<<<ggrid, 256>>>(nullptr, conv_w + (size_t)l * DD * DD,
                                    nullptr, /*a_sel=*/1, /*c_sel=*/1, /*relu=*/0);
        // fused: self-loop + neighbor gather + bias + relu
        aggregate_kernel<<<agg_blocks, 256>>>(conv_b + l * DD,
                                              out, /*o_sel=*/(l == 0) ? 0 : 1);
    }
}

// round 9
// speedup vs baseline: 1.1311x; 1.0720x over previous
#include <cuda_runtime.h>
#include <cuda_fp16.h>
#include <cstdint>

#define NN 50000
#define NE 800000
#define DD 256
#define SCAN_BLK 512
#define SCAN_NB  ((NN + SCAN_BLK - 1) / SCAN_BLK)   // 98
#define AST 140   // smem row stride (words): conflict-free mma fragment loads

// Static scratch (no allocations allowed): ~88 MB.
__device__ float g_x[NN * DD];                      // fp32 activations
__device__ __align__(16) __half g_hh[NN * DD];      // fp16 post-GEMM h
__device__ float g_dinv[NN];
__device__ int   g_src[NE];
__device__ int   g_dst[NE];
__device__ int   g_esrc[NE];        // CSR: src ids grouped by dst
__device__ int   g_cnt[NN];         // in-degree (edges only)
__device__ int   g_rowstart[NN + 1];
__device__ int   g_fill[NN];
__device__ int   g_bsum[SCAN_NB];
__device__ int   g_boff[SCAN_NB];
__device__ int   g_odd_nonzero;     // dtype sniffer flag

// ---------------------------------------------------------------------------
// Setup: dtype sniff, decode+histogram, 3-pass scan, CSR fill
// ---------------------------------------------------------------------------
__global__ void init_kernel() {
    int i = blockIdx.x * blockDim.x + threadIdx.x;
    if (i < NN) g_cnt[i] = 0;
    if (i == 0) g_odd_nonzero = 0;
}

// Sample first 8192 int32 words; int64 data => all odd words are zero.
__global__ void detect_kernel(const int* __restrict__ ei32) {
    int i = blockIdx.x * blockDim.x + threadIdx.x;   // 0..8191
    if ((i & 1) && ei32[i] != 0) atomicOr(&g_odd_nonzero, 1);
}

__global__ void decode_hist_kernel(const int* __restrict__ ei32) {
    int e = blockIdx.x * blockDim.x + threadIdx.x;
    if (e >= NE) return;
    int s, d;
    if (g_odd_nonzero) {            // genuinely int32: [src[NE] | dst[NE]]
        s = ei32[e];
        d = ei32[NE + e];
    } else {                        // int64: low words at even offsets
        s = ei32[2 * e];
        d = ei32[2 * (NE + e)];
    }
    g_src[e] = s;
    g_dst[e] = d;
    atomicAdd(&g_cnt[d], 1);
}

// Pass 1: per-block sums of g_cnt
__global__ void __launch_bounds__(SCAN_BLK) partial_sum_kernel() {
    __shared__ int s[SCAN_BLK];
    int t = threadIdx.x;
    int i = blockIdx.x * SCAN_BLK + t;
    s[t] = (i < NN) ? g_cnt[i] : 0;
    __syncthreads();
    for (int off = SCAN_BLK / 2; off > 0; off >>= 1) {
        if (t < off) s[t] += s[t + off];
        __syncthreads();
    }
    if (t == 0) g_bsum[blockIdx.x] = s[0];
}

// Pass 2: exclusive scan of 98 block sums (1 small block)
__global__ void __launch_bounds__(128) scan_partials_kernel() {
    __shared__ int s[128];
    int t = threadIdx.x;
    int v = (t < SCAN_NB) ? g_bsum[t] : 0;
    s[t] = v;
    __syncthreads();
    for (int off = 1; off < 128; off <<= 1) {
        int x = s[t];
        int add = (t >= off) ? s[t - off] : 0;
        __syncthreads();
        s[t] = x + add;
        __syncthreads();
    }
    if (t < SCAN_NB) g_boff[t] = s[t] - v;   // exclusive
}

// Pass 3: per-block local scan + offset; writes rowstart, dinv, fill
__global__ void __launch_bounds__(SCAN_BLK) write_rows_kernel() {
    __shared__ int s[SCAN_BLK];
    int t = threadIdx.x;
    int i = blockIdx.x * SCAN_BLK + t;
    int v = (i < NN) ? g_cnt[i] : 0;
    s[t] = v;
    __syncthreads();
    for (int off = 1; off < SCAN_BLK; off <<= 1) {
        int x = s[t];
        int add = (t >= off) ? s[t - off] : 0;
        __syncthreads();
        s[t] = x + add;
        __syncthreads();
    }
    if (i < NN) {
        g_rowstart[i] = g_boff[blockIdx.x] + s[t] - v;
        g_fill[i] = 0;
        g_dinv[i] = rsqrtf((float)v + 1.0f);   // +1 self loop
    }
    if (i == 0) g_rowstart[NN] = NE;
}

__global__ void fill_kernel() {
    int e = blockIdx.x * blockDim.x + threadIdx.x;
    if (e >= NE) return;
    int d = g_dst[e];
    int pos = g_rowstart[d] + atomicAdd(&g_fill[d], 1);
    g_esrc[pos] = g_src[e];
}

// ---------------------------------------------------------------------------
// TF32 tensor-core GEMM: C[M,256] = A[M,256] @ B[256,256] (+bias, +relu)
// 128x128 tile, 256 threads (8 warps, 2M x 4N), warp tile 64x32,
// mma.sync.m16n8k8.tf32, BK=16, register-prefetch pipeline (single smem buf).
// a_sel: 0 -> A = Ain (external), 1 -> A = g_x
// c_sel: 0 -> C = g_x (fp32),     1 -> C = g_hh (fp16)
// ---------------------------------------------------------------------------
__device__ __forceinline__ uint32_t f2tf32(float f) {
    uint32_t u;
    asm("cvt.rna.tf32.f32 %0, %1;" : "=r"(u) : "f"(f));
    return u;
}

__global__ void __launch_bounds__(256)
gemm_kernel(const float* __restrict__ Ain, const float* __restrict__ B,
            const float* __restrict__ bias, int a_sel, int c_sel, int relu)
{
    const float* A = (a_sel == 0) ? Ain : g_x;

    __shared__ uint32_t As[16 * AST];   // [k][m], tf32 bits
    __shared__ uint32_t Bs[16 * AST];   // [k][n], tf32 bits

    const int tid  = threadIdx.x;
    const int lane = tid & 31;
    const int w    = tid >> 5;
    const int mw   = (w & 1) << 6;      // warp M offset: 0 / 64
    const int nw   = (w >> 1) << 5;     // warp N offset: 0/32/64/96
    const int gid  = lane >> 2;         // 0..7
    const int tg   = lane & 3;          // 0..3
    const int row0 = blockIdx.x * 128;
    const int col0 = blockIdx.y * 128;

    float acc[4][4][4];
#pragma unroll
    for (int mt = 0; mt < 4; mt++)
#pragma unroll
        for (int nt = 0; nt < 4; nt++)
#pragma unroll
            for (int q = 0; q < 4; q++) acc[mt][nt][q] = 0.0f;

    float4 av[2], bv[2];

    // prefetch chunk 0
#pragma unroll
    for (int i = 0; i < 2; i++) {
        int idx = tid + i * 256;
        int r = row0 + (idx >> 2);
        int kq = idx & 3;
        av[i] = (r < NN) ? *(const float4*)&A[(size_t)r * DD + kq * 4]
                         : make_float4(0.f, 0.f, 0.f, 0.f);
        int kr = idx >> 5, nq = idx & 31;
        bv[i] = *(const float4*)&B[(size_t)kr * DD + col0 + nq * 4];
    }

    for (int c = 0; c < 16; c++) {
        __syncthreads();
        // store prefetched chunk to smem (cvt to tf32)
#pragma unroll
        for (int i = 0; i < 2; i++) {
            int idx = tid + i * 256;
            int r = idx >> 2, kq = idx & 3;
            As[(kq * 4 + 0) * AST + r] = f2tf32(av[i].x);
            As[(kq * 4 + 1) * AST + r] = f2tf32(av[i].y);
            As[(kq * 4 + 2) * AST + r] = f2tf32(av[i].z);
            As[(kq * 4 + 3) * AST + r] = f2tf32(av[i].w);
            int kr = idx >> 5, nq = idx & 31;
            uint4 bu;
            bu.x = f2tf32(bv[i].x); bu.y = f2tf32(bv[i].y);
            bu.z = f2tf32(bv[i].z); bu.w = f2tf32(bv[i].w);
            *(uint4*)&Bs[kr * AST + nq * 4] = bu;
        }
        __syncthreads();
        // prefetch next chunk (latency hidden behind MMAs below)
        if (c < 15) {
            int k0 = (c + 1) * 16;
#pragma unroll
            for (int i = 0; i < 2; i++) {
                int idx = tid + i * 256;
                int r = row0 + (idx >> 2);
                int kq = idx & 3;
                av[i] = (r < NN) ? *(const float4*)&A[(size_t)r * DD + k0 + kq * 4]
                                 : make_float4(0.f, 0.f, 0.f, 0.f);
                int kr = idx >> 5, nq = idx & 31;
                bv[i] = *(const float4*)&B[(size_t)(k0 + kr) * DD + col0 + nq * 4];
            }
        }
        // compute: 2 k8-substeps, 4x4 mma each
#pragma unroll
        for (int sub = 0; sub < 16; sub += 8) {
            uint32_t bf[4][2];
#pragma unroll
            for (int nt = 0; nt < 4; nt++) {
                bf[nt][0] = Bs[(sub + tg) * AST + nw + nt * 8 + gid];
                bf[nt][1] = Bs[(sub + tg + 4) * AST + nw + nt * 8 + gid];
            }
#pragma unroll
            for (int mt = 0; mt < 4; mt++) {
                uint32_t a0 = As[(sub + tg) * AST + mw + mt * 16 + gid];
                uint32_t a1 = As[(sub + tg) * AST + mw + mt * 16 + gid + 8];
                uint32_t a2 = As[(sub + tg + 4) * AST + mw + mt * 16 + gid];
                uint32_t a3 = As[(sub + tg + 4) * AST + mw + mt * 16 + gid + 8];
#pragma unroll
                for (int nt = 0; nt < 4; nt++) {
                    asm("mma.sync.aligned.m16n8k8.row.col.f32.tf32.tf32.f32 "
                        "{%0,%1,%2,%3}, {%4,%5,%6,%7}, {%8,%9}, {%0,%1,%2,%3};"
                        : "+f"(acc[mt][nt][0]), "+f"(acc[mt][nt][1]),
                          "+f"(acc[mt][nt][2]), "+f"(acc[mt][nt][3])
                        : "r"(a0), "r"(a1), "r"(a2), "r"(a3),
                          "r"(bf[nt][0]), "r"(bf[nt][1]));
                }
            }
        }
    }

    // epilogue: c0,c1 -> (row gid, cols 2tg,2tg+1); c2,c3 -> row gid+8
    float2 bb[4];
    if (bias) {
#pragma unroll
        for (int nt = 0; nt < 4; nt++) {
            int cc = col0 + nw + nt * 8 + 2 * tg;
            bb[nt].x = bias[cc];
            bb[nt].y = bias[cc + 1];
        }
    }
#pragma unroll
    for (int mt = 0; mt < 4; mt++) {
        int r = row0 + mw + mt * 16 + gid;
#pragma unroll
        for (int nt = 0; nt < 4; nt++) {
            int cc = col0 + nw + nt * 8 + 2 * tg;
            float2 v0 = make_float2(acc[mt][nt][0], acc[mt][nt][1]);
            float2 v1 = make_float2(acc[mt][nt][2], acc[mt][nt][3]);
            if (bias) {
                v0.x += bb[nt].x; v0.y += bb[nt].y;
                v1.x += bb[nt].x; v1.y += bb[nt].y;
            }
            if (relu) {
                v0.x = fmaxf(v0.x, 0.f); v0.y = fmaxf(v0.y, 0.f);
                v1.x = fmaxf(v1.x, 0.f); v1.y = fmaxf(v1.y, 0.f);
            }
            if (c_sel == 0) {
                if (r < NN)     *(float2*)&g_x[(size_t)r * DD + cc]       = v0;
                if (r + 8 < NN) *(float2*)&g_x[(size_t)(r + 8) * DD + cc] = v1;
            } else {
                if (r < NN)     *(__half2*)&g_hh[(size_t)r * DD + cc]       = __floats2half2_rn(v0.x, v0.y);
                if (r + 8 < NN) *(__half2*)&g_hh[(size_t)(r + 8) * DD + cc] = __floats2half2_rn(v1.x, v1.y);
            }
        }
    }
}

// ---------------------------------------------------------------------------
// Fused CSR aggregation (fp16 h): one warp per dst node, 4-edge unroll.
//   o[d] = relu( bias + dinv[d]^2 * h[d] + sum_{s in N(d)} dinv[s]dinv[d] h[s] )
// Lane holds 8 contiguous cols [lane*8, lane*8+8): ONE uint4 load per edge-row.
// ---------------------------------------------------------------------------
__device__ __forceinline__ void acc8(float* a, uint4 raw, float n) {
    const __half2* h2 = (const __half2*)&raw;
#pragma unroll
    for (int j = 0; j < 4; j++) {
        float2 f = __half22float2(h2[j]);
        a[2 * j + 0] += n * f.x;
        a[2 * j + 1] += n * f.y;
    }
}

__global__ void __launch_bounds__(256)
aggregate_kernel(const float* __restrict__ bias, float* __restrict__ Oin, int o_sel)
{
    float* o = (o_sel == 0) ? g_x : Oin;
    int warp = (blockIdx.x * blockDim.x + threadIdx.x) >> 5;
    int lane = threadIdx.x & 31;
    if (warp >= NN) return;
    const int d = warp;
    const float dv = g_dinv[d];

    float a[8];
    // self-loop init
    {
        uint4 raw = *((const uint4*)(g_hh + (size_t)d * DD) + lane);
        const __half2* h2 = (const __half2*)&raw;
        const float s2 = dv * dv;
#pragma unroll
        for (int j = 0; j < 4; j++) {
            float2 f = __half22float2(h2[j]);
            a[2 * j + 0] = s2 * f.x;
            a[2 * j + 1] = s2 * f.y;
        }
    }

    const int start = g_rowstart[d];
    const int end   = g_rowstart[d + 1];
    int i = start;
    for (; i + 4 <= end; i += 4) {
        int   s0 = g_esrc[i],     s1 = g_esrc[i + 1];
        int   s2 = g_esrc[i + 2], s3 = g_esrc[i + 3];
        float n0 = dv * g_dinv[s0], n1 = dv * g_dinv[s1];
        float n2 = dv * g_dinv[s2], n3 = dv * g_dinv[s3];
        uint4 r0 = *((const uint4*)(g_hh + (size_t)s0 * DD) + lane);
        uint4 r1 = *((const uint4*)(g_hh + (size_t)s1 * DD) + lane);
        uint4 r2 = *((const uint4*)(g_hh + (size_t)s2 * DD) + lane);
        uint4 r3 = *((const uint4*)(g_hh + (size_t)s3 * DD) + lane);
        acc8(a, r0, n0);
        acc8(a, r1, n1);
        acc8(a, r2, n2);
        acc8(a, r3, n3);
    }
    for (; i < end; i++) {
        int s0 = g_esrc[i];
        float n0 = dv * g_dinv[s0];
        uint4 r0 = *((const uint4*)(g_hh + (size_t)s0 * DD) + lane);
        acc8(a, r0, n0);
    }

    // bias + relu + store (cols lane*8 .. lane*8+7)
    const int cbase = lane * 8;
    float4 b0 = *(const float4*)&bias[cbase];
    float4 b1 = *(const float4*)&bias[cbase + 4];
    float4 v0, v1;
    v0.x = fmaxf(a[0] + b0.x, 0.f); v0.y = fmaxf(a[1] + b0.y, 0.f);
    v0.z = fmaxf(a[2] + b0.z, 0.f); v0.w = fmaxf(a[3] + b0.w, 0.f);
    v1.x = fmaxf(a[4] + b1.x, 0.f); v1.y = fmaxf(a[5] + b1.y, 0.f);
    v1.z = fmaxf(a[6] + b1.z, 0.f); v1.w = fmaxf(a[7] + b1.w, 0.f);
    float* orow = o + (size_t)d * DD + cbase;
    *(float4*)&orow[0] = v0;
    *(float4*)&orow[4] = v1;
}

// ---------------------------------------------------------------------------
// Launch — kernels only; no runtime API calls (graph-capture safe).
// ---------------------------------------------------------------------------
extern "C" void kernel_launch(void* const* d_in, const int* in_sizes, int n_in,
                              void* d_out, int out_size)
{
    const float* input  = (const float*)d_in[0];
    const int*   ei32   = (const int*)d_in[1];     // int32 view; dtype sniffed on device
    const float* weight = (const float*)d_in[2];
    const float* bias   = (const float*)d_in[3];
    const float* conv_w = (const float*)d_in[4];
    const float* conv_b = (const float*)d_in[5];
    float*       out    = (float*)d_out;

    // CSR build
    init_kernel<<<(NN + 255) / 256, 256>>>();
    detect_kernel<<<8192 / 256, 256>>>(ei32);
    decode_hist_kernel<<<(NE + 255) / 256, 256>>>(ei32);
    partial_sum_kernel<<<SCAN_NB, SCAN_BLK>>>();
    scan_partials_kernel<<<1, 128>>>();
    write_rows_kernel<<<SCAN_NB, SCAN_BLK>>>();
    fill_kernel<<<(NE + 255) / 256, 256>>>();

    dim3 ggrid((NN + 127) / 128, DD / 128);

    // x = relu(input @ W + b)   (A = input, C = g_x fp32)
    gemm_kernel<<<ggrid, 256>>>(input, weight, bias, /*a_sel=*/0, /*c_sel=*/0, /*relu=*/1);

    const int agg_blocks = (NN * 32 + 255) / 256;   // warp per node
    for (int l = 0; l < 2; l++) {
        // h = x @ conv_w[l]   (A = g_x, C = g_hh fp16)
        gemm_kernel<<<ggrid, 256>>>(nullptr, conv_w + (size_t)l * DD * DD,
                                    nullptr, /*a_sel=*/1, /*c_sel=*/1, /*relu=*/0);
        // fused: self-loop + neighbor gather + bias + relu
        aggregate_kernel<<<agg_blocks, 256>>>(conv_b + l * DD,
                                              out, /*o_sel=*/(l == 0) ? 0 : 1);
    }
}

// round 11
// speedup vs baseline: 1.5012x; 1.3272x over previous
#include <cuda_runtime.h>
#include <cuda_fp16.h>
#include <cstdint>

#define NN 50000
#define NE 800000
#define DD 256
#define SCAN_BLK 512
#define SCAN_NB  ((NN + SCAN_BLK - 1) / SCAN_BLK)   // 98
#define ASW 12    // As row stride in words (16 halves + pad) - conflict-free A frags
#define BSW 136   // Bs2 row stride in words (128 half2 + pad) - conflict-free B frags

// Static scratch (no allocations allowed): ~88 MB.
__device__ float g_x[NN * DD];                      // fp32 activations
__device__ __align__(16) __half g_hh[NN * DD];      // fp16 post-GEMM h
__device__ float g_dinv[NN];
__device__ int   g_src[NE];
__device__ int   g_dst[NE];
__device__ int   g_esrc[NE];        // CSR: src ids grouped by dst
__device__ int   g_cnt[NN];         // in-degree (edges only)
__device__ int   g_rowstart[NN + 1];
__device__ int   g_fill[NN];
__device__ int   g_bsum[SCAN_NB];
__device__ int   g_boff[SCAN_NB];
__device__ int   g_odd_nonzero;     // dtype sniffer flag

// bitcast __half2 -> uint32_t (no intrinsic exists for this direction)
__device__ __forceinline__ uint32_t h2u(__half2 h) {
    union { __half2 h; uint32_t u; } c;
    c.h = h;
    return c.u;
}

// ---------------------------------------------------------------------------
// Setup: dtype sniff, decode+histogram, 3-pass scan, CSR fill
// ---------------------------------------------------------------------------
__global__ void init_kernel() {
    int i = blockIdx.x * blockDim.x + threadIdx.x;
    if (i < NN) g_cnt[i] = 0;
    if (i == 0) g_odd_nonzero = 0;
}

// Sample first 8192 int32 words; int64 data => all odd words are zero.
__global__ void detect_kernel(const int* __restrict__ ei32) {
    int i = blockIdx.x * blockDim.x + threadIdx.x;   // 0..8191
    if ((i & 1) && ei32[i] != 0) atomicOr(&g_odd_nonzero, 1);
}

__global__ void decode_hist_kernel(const int* __restrict__ ei32) {
    int e = blockIdx.x * blockDim.x + threadIdx.x;
    if (e >= NE) return;
    int s, d;
    if (g_odd_nonzero) {            // genuinely int32: [src[NE] | dst[NE]]
        s = ei32[e];
        d = ei32[NE + e];
    } else {                        // int64: low words at even offsets
        s = ei32[2 * e];
        d = ei32[2 * (NE + e)];
    }
    g_src[e] = s;
    g_dst[e] = d;
    atomicAdd(&g_cnt[d], 1);
}

// Pass 1: per-block sums of g_cnt
__global__ void __launch_bounds__(SCAN_BLK) partial_sum_kernel() {
    __shared__ int s[SCAN_BLK];
    int t = threadIdx.x;
    int i = blockIdx.x * SCAN_BLK + t;
    s[t] = (i < NN) ? g_cnt[i] : 0;
    __syncthreads();
    for (int off = SCAN_BLK / 2; off > 0; off >>= 1) {
        if (t < off) s[t] += s[t + off];
        __syncthreads();
    }
    if (t == 0) g_bsum[blockIdx.x] = s[0];
}

// Pass 2: exclusive scan of 98 block sums (1 small block)
__global__ void __launch_bounds__(128) scan_partials_kernel() {
    __shared__ int s[128];
    int t = threadIdx.x;
    int v = (t < SCAN_NB) ? g_bsum[t] : 0;
    s[t] = v;
    __syncthreads();
    for (int off = 1; off < 128; off <<= 1) {
        int x = s[t];
        int add = (t >= off) ? s[t - off] : 0;
        __syncthreads();
        s[t] = x + add;
        __syncthreads();
    }
    if (t < SCAN_NB) g_boff[t] = s[t] - v;   // exclusive
}

// Pass 3: per-block local scan + offset; writes rowstart, dinv, fill
__global__ void __launch_bounds__(SCAN_BLK) write_rows_kernel() {
    __shared__ int s[SCAN_BLK];
    int t = threadIdx.x;
    int i = blockIdx.x * SCAN_BLK + t;
    int v = (i < NN) ? g_cnt[i] : 0;
    s[t] = v;
    __syncthreads();
    for (int off = 1; off < SCAN_BLK; off <<= 1) {
        int x = s[t];
        int add = (t >= off) ? s[t - off] : 0;
        __syncthreads();
        s[t] = x + add;
        __syncthreads();
    }
    if (i < NN) {
        g_rowstart[i] = g_boff[blockIdx.x] + s[t] - v;
        g_fill[i] = 0;
        g_dinv[i] = rsqrtf((float)v + 1.0f);   // +1 self loop
    }
    if (i == 0) g_rowstart[NN] = NE;
}

__global__ void fill_kernel() {
    int e = blockIdx.x * blockDim.x + threadIdx.x;
    if (e >= NE) return;
    int d = g_dst[e];
    int pos = g_rowstart[d] + atomicAdd(&g_fill[d], 1);
    g_esrc[pos] = g_src[e];
}

// ---------------------------------------------------------------------------
// FP16 tensor-core GEMM: C[M,256] = A[M,256] @ B[256,256] (+bias, +relu)
// 128x128 tile, 256 threads (8 warps, 2M x 4N), warp tile 64x32,
// mma.sync.m16n8k16.f16 (fp32 accum), BK=16, register-prefetch pipeline.
//   As[m][k]   halves, stride ASW words: A-frag = 1x LDS.32, conflict-free
//   Bs2[kp][n] half2 {B[2kp][n],B[2kp+1][n]}, stride BSW words: B-frag = 1x LDS.32
// a_sel: 0 -> A = Ain (external), 1 -> A = g_x
// c_sel: 0 -> C = g_x (fp32),     1 -> C = g_hh (fp16)
// ---------------------------------------------------------------------------
__global__ void __launch_bounds__(256)
gemm_kernel(const float* __restrict__ Ain, const float* __restrict__ B,
            const float* __restrict__ bias, int a_sel, int c_sel, int relu)
{
    const float* A = (a_sel == 0) ? Ain : g_x;

    __shared__ uint32_t As[128 * ASW];   // [m][k] halves (packed half2 words)
    __shared__ uint32_t Bs2[8 * BSW];    // [kpair][n] half2

    const int tid  = threadIdx.x;
    const int lane = tid & 31;
    const int w    = tid >> 5;
    const int mw   = (w & 1) << 6;      // warp M offset: 0 / 64
    const int nw   = (w >> 1) << 5;     // warp N offset: 0/32/64/96
    const int gid  = lane >> 2;         // 0..7
    const int tg   = lane & 3;          // 0..3
    const int row0 = blockIdx.x * 128;
    const int col0 = blockIdx.y * 128;

    // A staging indices: idx in [0,512): r = idx>>2 (row), kq = (idx&3)*4 (k float offset)
    const int ar0 = tid >> 2,          ak0 = (tid & 3) * 4;
    const int ar1 = (tid + 256) >> 2,  ak1 = ak0;   // (idx+256)&3 == idx&3
    // B staging: p = tid>>5 (k-pair 0..7), n4 = (tid&31)*4
    const int bp  = tid >> 5;
    const int bn4 = (tid & 31) * 4;

    float acc[4][4][4];
#pragma unroll
    for (int mt = 0; mt < 4; mt++)
#pragma unroll
        for (int nt = 0; nt < 4; nt++)
#pragma unroll
            for (int q = 0; q < 4; q++) acc[mt][nt][q] = 0.0f;

    float4 av0, av1, bv0, bv1;

    // prefetch chunk 0
    {
        int r0 = row0 + ar0, r1 = row0 + ar1;
        av0 = (r0 < NN) ? *(const float4*)&A[(size_t)r0 * DD + ak0] : make_float4(0,0,0,0);
        av1 = (r1 < NN) ? *(const float4*)&A[(size_t)r1 * DD + ak1] : make_float4(0,0,0,0);
        bv0 = *(const float4*)&B[(size_t)(2 * bp)     * DD + col0 + bn4];
        bv1 = *(const float4*)&B[(size_t)(2 * bp + 1) * DD + col0 + bn4];
    }

    for (int c = 0; c < 16; c++) {
        __syncthreads();
        // store prefetched chunk to smem (cvt to fp16)
        {
            uint2 aw;
            aw.x = h2u(__floats2half2_rn(av0.x, av0.y));
            aw.y = h2u(__floats2half2_rn(av0.z, av0.w));
            *(uint2*)&As[ar0 * ASW + (ak0 >> 1)] = aw;
            aw.x = h2u(__floats2half2_rn(av1.x, av1.y));
            aw.y = h2u(__floats2half2_rn(av1.z, av1.w));
            *(uint2*)&As[ar1 * ASW + (ak1 >> 1)] = aw;
            uint4 bw;
            bw.x = h2u(__floats2half2_rn(bv0.x, bv1.x));
            bw.y = h2u(__floats2half2_rn(bv0.y, bv1.y));
            bw.z = h2u(__floats2half2_rn(bv0.z, bv1.z));
            bw.w = h2u(__floats2half2_rn(bv0.w, bv1.w));
            *(uint4*)&Bs2[bp * BSW + bn4] = bw;
        }
        __syncthreads();
        // prefetch next chunk (latency hidden behind MMAs below)
        if (c < 15) {
            int k0 = (c + 1) * 16;
            int r0 = row0 + ar0, r1 = row0 + ar1;
            av0 = (r0 < NN) ? *(const float4*)&A[(size_t)r0 * DD + k0 + ak0] : make_float4(0,0,0,0);
            av1 = (r1 < NN) ? *(const float4*)&A[(size_t)r1 * DD + k0 + ak1] : make_float4(0,0,0,0);
            bv0 = *(const float4*)&B[(size_t)(k0 + 2 * bp)     * DD + col0 + bn4];
            bv1 = *(const float4*)&B[(size_t)(k0 + 2 * bp + 1) * DD + col0 + bn4];
        }
        // compute chunk c: one k16 step, 4x4 mma m16n8k16
        {
            uint32_t bf[4][2];
#pragma unroll
            for (int nt = 0; nt < 4; nt++) {
                int n = nw + nt * 8 + gid;
                bf[nt][0] = Bs2[tg * BSW + n];          // k = 2tg, 2tg+1
                bf[nt][1] = Bs2[(tg + 4) * BSW + n];    // k = 2tg+8, 2tg+9
            }
#pragma unroll
            for (int mt = 0; mt < 4; mt++) {
                int m = mw + mt * 16 + gid;
                uint32_t a0 = As[m * ASW + tg];             // A[m][2tg..2tg+1]
                uint32_t a1 = As[(m + 8) * ASW + tg];       // A[m+8][2tg..]
                uint32_t a2 = As[m * ASW + tg + 4];         // A[m][2tg+8..]
                uint32_t a3 = As[(m + 8) * ASW + tg + 4];   // A[m+8][2tg+8..]
#pragma unroll
                for (int nt = 0; nt < 4; nt++) {
                    asm("mma.sync.aligned.m16n8k16.row.col.f32.f16.f16.f32 "
                        "{%0,%1,%2,%3}, {%4,%5,%6,%7}, {%8,%9}, {%0,%1,%2,%3};"
                        : "+f"(acc[mt][nt][0]), "+f"(acc[mt][nt][1]),
                          "+f"(acc[mt][nt][2]), "+f"(acc[mt][nt][3])
                        : "r"(a0), "r"(a1), "r"(a2), "r"(a3),
                          "r"(bf[nt][0]), "r"(bf[nt][1]));
                }
            }
        }
    }

    // epilogue: c0,c1 -> (row gid, cols 2tg,2tg+1); c2,c3 -> row gid+8
    float2 bb[4];
    if (bias) {
#pragma unroll
        for (int nt = 0; nt < 4; nt++) {
            int cc = col0 + nw + nt * 8 + 2 * tg;
            bb[nt].x = bias[cc];
            bb[nt].y = bias[cc + 1];
        }
    }
#pragma unroll
    for (int mt = 0; mt < 4; mt++) {
        int r = row0 + mw + mt * 16 + gid;
#pragma unroll
        for (int nt = 0; nt < 4; nt++) {
            int cc = col0 + nw + nt * 8 + 2 * tg;
            float2 v0 = make_float2(acc[mt][nt][0], acc[mt][nt][1]);
            float2 v1 = make_float2(acc[mt][nt][2], acc[mt][nt][3]);
            if (bias) {
                v0.x += bb[nt].x; v0.y += bb[nt].y;
                v1.x += bb[nt].x; v1.y += bb[nt].y;
            }
            if (relu) {
                v0.x = fmaxf(v0.x, 0.f); v0.y = fmaxf(v0.y, 0.f);
                v1.x = fmaxf(v1.x, 0.f); v1.y = fmaxf(v1.y, 0.f);
            }
            if (c_sel == 0) {
                if (r < NN)     *(float2*)&g_x[(size_t)r * DD + cc]       = v0;
                if (r + 8 < NN) *(float2*)&g_x[(size_t)(r + 8) * DD + cc] = v1;
            } else {
                if (r < NN)     *(__half2*)&g_hh[(size_t)r * DD + cc]       = __floats2half2_rn(v0.x, v0.y);
                if (r + 8 < NN) *(__half2*)&g_hh[(size_t)(r + 8) * DD + cc] = __floats2half2_rn(v1.x, v1.y);
            }
        }
    }
}

// ---------------------------------------------------------------------------
// Fused CSR aggregation (fp16 h): one warp per dst node, 4-edge unroll.
//   o[d] = relu( bias + dinv[d]^2 * h[d] + sum_{s in N(d)} dinv[s]dinv[d] h[s] )
// Lane holds 8 contiguous cols [lane*8, lane*8+8): ONE uint4 load per edge-row.
// ---------------------------------------------------------------------------
__device__ __forceinline__ void acc8(float* a, uint4 raw, float n) {
    const __half2* h2 = (const __half2*)&raw;
#pragma unroll
    for (int j = 0; j < 4; j++) {
        float2 f = __half22float2(h2[j]);
        a[2 * j + 0] += n * f.x;
        a[2 * j + 1] += n * f.y;
    }
}

__global__ void __launch_bounds__(256)
aggregate_kernel(const float* __restrict__ bias, float* __restrict__ Oin, int o_sel)
{
    float* o = (o_sel == 0) ? g_x : Oin;
    int warp = (blockIdx.x * blockDim.x + threadIdx.x) >> 5;
    int lane = threadIdx.x & 31;
    if (warp >= NN) return;
    const int d = warp;
    const float dv = g_dinv[d];

    float a[8];
    // self-loop init
    {
        uint4 raw = *((const uint4*)(g_hh + (size_t)d * DD) + lane);
        const __half2* h2 = (const __half2*)&raw;
        const float s2 = dv * dv;
#pragma unroll
        for (int j = 0; j < 4; j++) {
            float2 f = __half22float2(h2[j]);
            a[2 * j + 0] = s2 * f.x;
            a[2 * j + 1] = s2 * f.y;
        }
    }

    const int start = g_rowstart[d];
    const int end   = g_rowstart[d + 1];
    int i = start;
    for (; i + 4 <= end; i += 4) {
        int   s0 = g_esrc[i],     s1 = g_esrc[i + 1];
        int   s2 = g_esrc[i + 2], s3 = g_esrc[i + 3];
        float n0 = dv * g_dinv[s0], n1 = dv * g_dinv[s1];
        float n2 = dv * g_dinv[s2], n3 = dv * g_dinv[s3];
        uint4 r0 = *((const uint4*)(g_hh + (size_t)s0 * DD) + lane);
        uint4 r1 = *((const uint4*)(g_hh + (size_t)s1 * DD) + lane);
        uint4 r2 = *((const uint4*)(g_hh + (size_t)s2 * DD) + lane);
        uint4 r3 = *((const uint4*)(g_hh + (size_t)s3 * DD) + lane);
        acc8(a, r0, n0);
        acc8(a, r1, n1);
        acc8(a, r2, n2);
        acc8(a, r3, n3);
    }
    for (; i < end; i++) {
        int s0 = g_esrc[i];
        float n0 = dv * g_dinv[s0];
        uint4 r0 = *((const uint4*)(g_hh + (size_t)s0 * DD) + lane);
        acc8(a, r0, n0);
    }

    // bias + relu + store (cols lane*8 .. lane*8+7)
    const int cbase = lane * 8;
    float4 b0 = *(const float4*)&bias[cbase];
    float4 b1 = *(const float4*)&bias[cbase + 4];
    float4 v0, v1;
    v0.x = fmaxf(a[0] + b0.x, 0.f); v0.y = fmaxf(a[1] + b0.y, 0.f);
    v0.z = fmaxf(a[2] + b0.z, 0.f); v0.w = fmaxf(a[3] + b0.w, 0.f);
    v1.x = fmaxf(a[4] + b1.x, 0.f); v1.y = fmaxf(a[5] + b1.y, 0.f);
    v1.z = fmaxf(a[6] + b1.z, 0.f); v1.w = fmaxf(a[7] + b1.w, 0.f);
    float* orow = o + (size_t)d * DD + cbase;
    *(float4*)&orow[0] = v0;
    *(float4*)&orow[4] = v1;
}

// ---------------------------------------------------------------------------
// Launch — kernels only; no runtime API calls (graph-capture safe).
// ---------------------------------------------------------------------------
extern "C" void kernel_launch(void* const* d_in, const int* in_sizes, int n_in,
                              void* d_out, int out_size)
{
    const float* input  = (const float*)d_in[0];
    const int*   ei32   = (const int*)d_in[1];     // int32 view; dtype sniffed on device
    const float* weight = (const float*)d_in[2];
    const float* bias   = (const float*)d_in[3];
    const float* conv_w = (const float*)d_in[4];
    const float* conv_b = (const float*)d_in[5];
    float*       out    = (float*)d_out;

    // CSR build
    init_kernel<<<(NN + 255) / 256, 256>>>();
    detect_kernel<<<8192 / 256, 256>>>(ei32);
    decode_hist_kernel<<<(NE + 255) / 256, 256>>>(ei32);
    partial_sum_kernel<<<SCAN_NB, SCAN_BLK>>>();
    scan_partials_kernel<<<1, 128>>>();
    write_rows_kernel<<<SCAN_NB, SCAN_BLK>>>();
    fill_kernel<<<(NE + 255) / 256, 256>>>();

    dim3 ggrid((NN + 127) / 128, DD / 128);

    // x = relu(input @ W + b)   (A = input, C = g_x fp32)
    gemm_kernel<<<ggrid, 256>>>(input, weight, bias, /*a_sel=*/0, /*c_sel=*/0, /*relu=*/1);

    const int agg_blocks = (NN * 32 + 255) / 256;   // warp per node
    for (int l = 0; l < 2; l++) {
        // h = x @ conv_w[l]   (A = g_x, C = g_hh fp16)
        gemm_kernel<<<ggrid, 256>>>(nullptr, conv_w + (size_t)l * DD * DD,
                                    nullptr, /*a_sel=*/1, /*c_sel=*/1, /*relu=*/0);
        // fused: self-loop + neighbor gather + bias + relu
        aggregate_kernel<<<agg_blocks, 256>>>(conv_b + l * DD,
                                              out, /*o_sel=*/(l == 0) ? 0 : 1);
    }
}